// round 11
// baseline (speedup 1.0000x reference)
#include <cuda_runtime.h>
#include <cstdint>

#define Bd 256
#define Sd 512
#define Cd 64
#define Hd 128
#define Gd 512
#define REC_THREADS 256
#define KR 80
#define QR 20
#define QS 12

typedef unsigned long long u64;
typedef unsigned int u32;

// ---------------- device global scratch ----------------
__device__ float g_xg[(size_t)Sd * Bd * Gd];      // gate preacts (reused by both layers)
__device__ float g_y1[(size_t)Sd * Bd * Hd];      // layer-0 h, tf32-rna rounded, m-major
__device__ float g_a0[(size_t)Sd * Bd * Cd];      // x, tf32-rna rounded, m-major
__device__ float g_w0t[(size_t)Gd * Cd];          // Wih0 tf32-rna
__device__ float g_w1t[(size_t)Gd * Hd];          // Wih1 tf32-rna
__device__ float g_bs0[Gd];
__device__ float g_bs1[Gd];

// ---------------- helpers ----------------
__device__ __forceinline__ void unpack2(u64 v, float& x, float& y) {
    asm("mov.b64 {%0,%1}, %2;" : "=f"(x), "=f"(y) : "l"(v));
}
__device__ __forceinline__ u64 fma2(u64 a, u64 b, u64 c) {
    u64 d; asm("fma.rn.f32x2 %0, %1, %2, %3;" : "=l"(d) : "l"(a), "l"(b), "l"(c)); return d;
}
__device__ __forceinline__ float tanh_fast(float x) {
    float y; asm("tanh.approx.f32 %0, %1;" : "=f"(y) : "f"(x)); return y;
}
__device__ __forceinline__ float hsum2(u64 v) { float a, b; unpack2(v, a, b); return a + b; }
__device__ __forceinline__ u32 to_tf32(float x) {
    u32 r; asm("cvt.rna.tf32.f32 %0, %1;" : "=r"(r) : "f"(x)); return r;
}
__device__ __forceinline__ void mma_tf32(
    float& c0, float& c1, float& c2, float& c3,
    u32 a0, u32 a1, u32 a2, u32 a3, u32 b0, u32 b1)
{
    asm("mma.sync.aligned.m16n8k8.row.col.f32.tf32.tf32.f32 "
        "{%0,%1,%2,%3}, {%4,%5,%6,%7}, {%8,%9}, {%0,%1,%2,%3};"
        : "+f"(c0), "+f"(c1), "+f"(c2), "+f"(c3)
        : "r"(a0), "r"(a1), "r"(a2), "r"(a3), "r"(b0), "r"(b1));
}
__device__ __forceinline__ void cp16(u32 dst, const void* src) {
    asm volatile("cp.async.cg.shared.global [%0], [%1], 16;" :: "r"(dst), "l"(src));
}
__device__ __forceinline__ u32 smem_u32(const void* p) {
    u32 a; asm("{ .reg .u64 t; cvta.to.shared.u64 t, %1; cvt.u32.u64 %0, t; }" : "=r"(a) : "l"(p));
    return a;
}

// ---------------- prep kernels (rna pre-rounding) ----------------
__global__ void prep_x_kernel(const float* __restrict__ x)
{
    int i = blockIdx.x * 256 + threadIdx.x;          // linear over x (B,S,C)
    if (i >= Bd * Sd * Cd) return;
    int k = i & (Cd - 1);
    int s = (i >> 6) & (Sd - 1);
    int b = i >> 15;
    int m = s * Bd + b;
    g_a0[(size_t)m * Cd + k] = __uint_as_float(to_tf32(x[i]));
}

__global__ void prep_w_kernel(const float* __restrict__ W, const float* __restrict__ b1,
                              const float* __restrict__ b2, float* __restrict__ wt,
                              float* __restrict__ bsum, int K)
{
    int i = blockIdx.x * 256 + threadIdx.x;
    if (i >= Gd * K) return;
    wt[i] = __uint_as_float(to_tf32(W[i]));
    if (i < Gd) bsum[i] = b1[i] + b2[i];
}

// ---------------------------------------------------------------------------
// Pipelined TF32 GEMM: out[m,g] = sum_k A[m,k]*W[g,k] + bsum[g]
// A, W pre-rounded to tf32 (rna) and m-major -> pure linear cp.async fills.
// CTA tile 128m x 128n, kc=32 double-buffered.
// Warps: 4(m) x 2(n); per warp 32m x 64n = 2 x 8 m16n8k8 tiles.
// Smem chunk: A [128][36], W [128][36]; banks (4*gID+tig) distinct.
// ---------------------------------------------------------------------------
template <int K>
__global__ __launch_bounds__(256) void gemm_tf32_kernel(
    const float* __restrict__ A, const float* __restrict__ Wt,
    const float* __restrict__ bsum, float* __restrict__ out)
{
    constexpr int KC = 32;
    constexpr int NC = K / KC;
    constexpr int SK = 36;
    constexpr int TBUF = 128 * SK;         // u32 per matrix per stage

    extern __shared__ u32 sm32[];
    const u32 sb = smem_u32(sm32);

    const int tid = threadIdx.x;
    const int mt  = blockIdx.x;
    const int nt  = blockIdx.y;

    auto fill = [&](int c, int buf) {
        const int k0 = c * KC;
#pragma unroll
        for (int r = 0; r < 4; r++) {
            int idx = tid + 256 * r;
            int row = idx >> 3, seg = idx & 7;
            cp16(sb + (u32)(buf * 2 * TBUF + row * SK + seg * 4) * 4,
                 A + (size_t)(mt * 128 + row) * K + k0 + seg * 4);
        }
#pragma unroll
        for (int r = 0; r < 4; r++) {
            int idx = tid + 256 * r;
            int row = idx >> 3, seg = idx & 7;
            cp16(sb + (u32)(buf * 2 * TBUF + TBUF + row * SK + seg * 4) * 4,
                 Wt + (size_t)(nt * 128 + row) * K + k0 + seg * 4);
        }
        asm volatile("cp.async.commit_group;" ::: "memory");
    };

    const int wid  = tid >> 5;
    const int lane = tid & 31;
    const int gID  = lane >> 2;
    const int tig  = lane & 3;
    const int wm   = (wid >> 1) * 32;     // 4 m-warps
    const int wn   = (wid & 1) * 64;      // 2 n-warps

    float c[2][8][4];
#pragma unroll
    for (int i = 0; i < 2; i++)
#pragma unroll
        for (int j = 0; j < 8; j++)
#pragma unroll
            for (int q = 0; q < 4; q++) c[i][j][q] = 0.0f;

    fill(0, 0);

    for (int ch = 0; ch < NC; ch++) {
        if (ch + 1 < NC) {
            fill(ch + 1, (ch + 1) & 1);
            asm volatile("cp.async.wait_group 1;" ::: "memory");
        } else {
            asm volatile("cp.async.wait_group 0;" ::: "memory");
        }
        __syncthreads();

        const u32* As = sm32 + (ch & 1) * 2 * TBUF;
        const u32* Bs = As + TBUF;

#pragma unroll
        for (int kb = 0; kb < KC / 8; kb++) {
            const int k0 = kb * 8;
            u32 a[2][4];
#pragma unroll
            for (int mi = 0; mi < 2; mi++) {
                int r = wm + mi * 16 + gID;
                a[mi][0] = As[r * SK + k0 + tig];
                a[mi][1] = As[(r + 8) * SK + k0 + tig];
                a[mi][2] = As[r * SK + k0 + tig + 4];
                a[mi][3] = As[(r + 8) * SK + k0 + tig + 4];
            }
            u32 b[8][2];
#pragma unroll
            for (int ni = 0; ni < 8; ni++) {
                int r = wn + ni * 8 + gID;
                b[ni][0] = Bs[r * SK + k0 + tig];
                b[ni][1] = Bs[r * SK + k0 + tig + 4];
            }
#pragma unroll
            for (int mi = 0; mi < 2; mi++)
#pragma unroll
                for (int ni = 0; ni < 8; ni++)
                    mma_tf32(c[mi][ni][0], c[mi][ni][1], c[mi][ni][2], c[mi][ni][3],
                             a[mi][0], a[mi][1], a[mi][2], a[mi][3],
                             b[ni][0], b[ni][1]);
        }
        __syncthreads();
    }

    // epilogue: bias + store
#pragma unroll
    for (int ni = 0; ni < 8; ni++) {
        int g = nt * 128 + wn + ni * 8 + 2 * tig;
        float2 bv = *(const float2*)&bsum[g];
#pragma unroll
        for (int mi = 0; mi < 2; mi++) {
            size_t m = (size_t)mt * 128 + wm + mi * 16 + gID;
            *(float2*)&out[m * Gd + g]       = make_float2(c[mi][ni][0] + bv.x, c[mi][ni][1] + bv.y);
            *(float2*)&out[(m + 8) * Gd + g] = make_float2(c[mi][ni][2] + bv.x, c[mi][ni][3] + bv.y);
        }
    }
}

// ---------------------------------------------------------------------------
// LSTM recurrence (proven core). YIMG: layer 0 writes rna-rounded h m-major
// into g_y1 (consumed by layer-1 GEMM); else writes only final h.
// ---------------------------------------------------------------------------
template <bool YIMG>
__global__ __launch_bounds__(REC_THREADS, 1) void lstm_rec_kernel(
    const float* __restrict__ xg, const float* __restrict__ Whh,
    float* __restrict__ y_all, float* __restrict__ y_last)
{
    extern __shared__ char smraw[];
    ulonglong2* Wq = (ulonglong2*)smraw;
    float* hb = (float*)(smraw + (size_t)QS * 2 * 256 * 16);

    const int t = threadIdx.x;
    const int u = t >> 1;
    const int p = t & 1;
    const int col0 = p * 128 + u;
    const int col1 = 256 + p * 128 + u;
    const int b0 = blockIdx.x * 2;

    u64 wA[2 * QR], wB[2 * QR];
    {
        const u64* rowA = (const u64*)(Whh + (size_t)col0 * Hd);
        const u64* rowB = (const u64*)(Whh + (size_t)col1 * Hd);
#pragma unroll
        for (int j = 0; j < 2 * QR; j++) { wA[j] = rowA[j]; wB[j] = rowB[j]; }
    }
#pragma unroll
    for (int j = 0; j < QS; j++) {
        Wq[(j * 2 + 0) * 256 + t] = *(const ulonglong2*)(Whh + (size_t)col0 * Hd + KR + 4 * j);
        Wq[(j * 2 + 1) * 256 + t] = *(const ulonglong2*)(Whh + (size_t)col1 * Hd + KR + 4 * j);
    }
    for (int i = t; i < 2 * 2 * 132; i += REC_THREADS) hb[i] = 0.0f;

    float c = 0.0f;
    __syncthreads();

    float xv00 = xg[(size_t)(b0)*Gd + col0];
    float xv01 = xg[(size_t)(b0 + 1) * Gd + col0];
    float xv10 = xg[(size_t)(b0)*Gd + col1];
    float xv11 = xg[(size_t)(b0 + 1) * Gd + col1];

    for (int s = 0; s < Sd; s++) {
        float n00 = 0.f, n01 = 0.f, n10 = 0.f, n11 = 0.f;
        if (s + 1 < Sd) {
            size_t base = (size_t)(s + 1) * Bd + b0;
            n00 = xg[base * Gd + col0];
            n01 = xg[(base + 1) * Gd + col0];
            n10 = xg[base * Gd + col1];
            n11 = xg[(base + 1) * Gd + col1];
        }
        const int ph = s & 1;
        const ulonglong2* hq0 = (const ulonglong2*)(hb + (ph * 2 + 0) * 132);
        const ulonglong2* hq1 = (const ulonglong2*)(hb + (ph * 2 + 1) * 132);

        u64 a00e = 0, a00o = 0, a01e = 0, a01o = 0;
        u64 a10e = 0, a10o = 0, a11e = 0, a11o = 0;

#pragma unroll
        for (int j = 0; j < QR; j++) {
            ulonglong2 hA = hq0[j], hB = hq1[j];
            a00e = fma2(wA[2 * j], hA.x, a00e);
            a00o = fma2(wA[2 * j + 1], hA.y, a00o);
            a01e = fma2(wA[2 * j], hB.x, a01e);
            a01o = fma2(wA[2 * j + 1], hB.y, a01o);
            a10e = fma2(wB[2 * j], hA.x, a10e);
            a10o = fma2(wB[2 * j + 1], hA.y, a10o);
            a11e = fma2(wB[2 * j], hB.x, a11e);
            a11o = fma2(wB[2 * j + 1], hB.y, a11o);
        }
#pragma unroll
        for (int j = 0; j < QS; j++) {
            ulonglong2 w0 = Wq[(j * 2 + 0) * 256 + t];
            ulonglong2 w1 = Wq[(j * 2 + 1) * 256 + t];
            ulonglong2 hA = hq0[QR + j], hB = hq1[QR + j];
            a00e = fma2(w0.x, hA.x, a00e);
            a00o = fma2(w0.y, hA.y, a00o);
            a01e = fma2(w0.x, hB.x, a01e);
            a01o = fma2(w0.y, hB.y, a01o);
            a10e = fma2(w1.x, hA.x, a10e);
            a10o = fma2(w1.y, hA.y, a10o);
            a11e = fma2(w1.x, hB.x, a11e);
            a11o = fma2(w1.y, hB.y, a11o);
        }

        float p00 = xv00 + hsum2(a00e) + hsum2(a00o);
        float p01 = xv01 + hsum2(a01e) + hsum2(a01o);
        float p10 = xv10 + hsum2(a10e) + hsum2(a10o);
        float p11 = xv11 + hsum2(a11e) + hsum2(a11o);

        float v00 = fmaf(0.5f, tanh_fast(0.5f * p00), 0.5f);
        float v01 = fmaf(0.5f, tanh_fast(0.5f * p01), 0.5f);
        float a10s = (p == 0) ? p10 : 0.5f * p10;
        float a11s = (p == 0) ? p11 : 0.5f * p11;
        float t10 = tanh_fast(a10s);
        float t11 = tanh_fast(a11s);
        float v10 = (p == 0) ? t10 : fmaf(0.5f, t10, 0.5f);
        float v11 = (p == 0) ? t11 : fmaf(0.5f, t11, 0.5f);

        float send1 = (p == 0) ? v01 : v00;
        float send2 = (p == 0) ? v11 : v10;
        float got1 = __shfl_xor_sync(0xffffffffu, send1, 1);
        float got2 = __shfl_xor_sync(0xffffffffu, send2, 1);

        float iv = (p == 0) ? v00 : got1;
        float fv = (p == 0) ? got1 : v01;
        float gv = (p == 0) ? v10 : got2;
        float ov = (p == 0) ? got2 : v11;

        c = fmaf(fv, c, iv * gv);
        float hn = ov * tanh_fast(c);

        hb[((ph ^ 1) * 2 + p) * 132 + u] = hn;
        if (YIMG) {
            // rna-rounded for the layer-1 tf32 GEMM
            y_all[((size_t)s * Bd + b0 + p) * Hd + u] = __uint_as_float(to_tf32(hn));
        } else if (s == Sd - 1) {
            y_last[(size_t)(b0 + p) * Hd + u] = hn;
        }

        xv00 = n00; xv01 = n01; xv10 = n10; xv11 = n11;
        __syncthreads();
    }
}

// ---------------------------------------------------------------------------
extern "C" void kernel_launch(void* const* d_in, const int* in_sizes, int n_in,
                              void* d_out, int out_size)
{
    const float* x    = (const float*)d_in[0];
    const float* Wih0 = (const float*)d_in[1];
    const float* Whh0 = (const float*)d_in[2];
    const float* bih0 = (const float*)d_in[3];
    const float* bhh0 = (const float*)d_in[4];
    const float* Wih1 = (const float*)d_in[5];
    const float* Whh1 = (const float*)d_in[6];
    const float* bih1 = (const float*)d_in[7];
    const float* bhh1 = (const float*)d_in[8];
    float* out = (float*)d_out;

    float *xg, *y1, *a0, *w0t, *w1t, *bs0, *bs1;
    cudaGetSymbolAddress((void**)&xg, g_xg);
    cudaGetSymbolAddress((void**)&y1, g_y1);
    cudaGetSymbolAddress((void**)&a0, g_a0);
    cudaGetSymbolAddress((void**)&w0t, g_w0t);
    cudaGetSymbolAddress((void**)&w1t, g_w1t);
    cudaGetSymbolAddress((void**)&bs0, g_bs0);
    cudaGetSymbolAddress((void**)&bs1, g_bs1);

    const int smem_gemm = 2 * 2 * 128 * 36 * 4;   // 73728 B
    const int smem_rec  = QS * 2 * 256 * 16 + 2 * 2 * 132 * (int)sizeof(float);

    cudaFuncSetAttribute((const void*)gemm_tf32_kernel<Cd>,
                         cudaFuncAttributeMaxDynamicSharedMemorySize, smem_gemm);
    cudaFuncSetAttribute((const void*)gemm_tf32_kernel<Hd>,
                         cudaFuncAttributeMaxDynamicSharedMemorySize, smem_gemm);
    cudaFuncSetAttribute((const void*)lstm_rec_kernel<true>,
                         cudaFuncAttributeMaxDynamicSharedMemorySize, smem_rec);
    cudaFuncSetAttribute((const void*)lstm_rec_kernel<false>,
                         cudaFuncAttributeMaxDynamicSharedMemorySize, smem_rec);

    // prep: rna pre-rounding + transpose + bias sums
    prep_x_kernel<<<(Bd * Sd * Cd + 255) / 256, 256>>>(x);
    prep_w_kernel<<<(Gd * Cd + 255) / 256, 256>>>(Wih0, bih0, bhh0, w0t, bs0, Cd);
    prep_w_kernel<<<(Gd * Hd + 255) / 256, 256>>>(Wih1, bih1, bhh1, w1t, bs1, Hd);

    dim3 ggrid((Sd * Bd) / 128, Gd / 128);

    // layer 0
    gemm_tf32_kernel<Cd><<<ggrid, 256, smem_gemm>>>(a0, w0t, bs0, xg);
    lstm_rec_kernel<true><<<Bd / 2, REC_THREADS, smem_rec>>>(xg, Whh0, y1, nullptr);

    // layer 1
    gemm_tf32_kernel<Hd><<<ggrid, 256, smem_gemm>>>(y1, w1t, bs1, xg);
    lstm_rec_kernel<false><<<Bd / 2, REC_THREADS, smem_rec>>>(xg, Whh1, nullptr, out);
}

// round 12
// speedup vs baseline: 1.0190x; 1.0190x over previous
#include <cuda_runtime.h>
#include <cuda_fp16.h>
#include <cstdint>

#define Bd 256
#define Sd 512
#define Cd 64
#define Hd 128
#define Gd 512
#define REC_THREADS 256
#define KR 80
#define QR 20
#define QS 12

typedef unsigned long long u64;
typedef unsigned int u32;

// ---------------- device global scratch ----------------
__device__ __half g_xg[(size_t)Sd * Bd * Gd];     // gate preacts, fp16 (both layers)
__device__ float  g_y1[(size_t)Sd * Bd * Hd];     // layer-0 h, tf32-rna, m-major
__device__ float  g_w0t[(size_t)Gd * Cd];         // Wih0 tf32-rna
__device__ float  g_w1t[(size_t)Gd * Hd];         // Wih1 tf32-rna
__device__ float  g_bs0[Gd];
__device__ float  g_bs1[Gd];

// ---------------- helpers ----------------
__device__ __forceinline__ void unpack2(u64 v, float& x, float& y) {
    asm("mov.b64 {%0,%1}, %2;" : "=f"(x), "=f"(y) : "l"(v));
}
__device__ __forceinline__ u64 fma2(u64 a, u64 b, u64 c) {
    u64 d; asm("fma.rn.f32x2 %0, %1, %2, %3;" : "=l"(d) : "l"(a), "l"(b), "l"(c)); return d;
}
__device__ __forceinline__ float tanh_fast(float x) {
    float y; asm("tanh.approx.f32 %0, %1;" : "=f"(y) : "f"(x)); return y;
}
__device__ __forceinline__ float hsum2(u64 v) { float a, b; unpack2(v, a, b); return a + b; }
__device__ __forceinline__ u32 to_tf32(float x) {
    u32 r; asm("cvt.rna.tf32.f32 %0, %1;" : "=r"(r) : "f"(x)); return r;
}
__device__ __forceinline__ void mma_tf32(
    float& c0, float& c1, float& c2, float& c3,
    u32 a0, u32 a1, u32 a2, u32 a3, u32 b0, u32 b1)
{
    asm("mma.sync.aligned.m16n8k8.row.col.f32.tf32.tf32.f32 "
        "{%0,%1,%2,%3}, {%4,%5,%6,%7}, {%8,%9}, {%0,%1,%2,%3};"
        : "+f"(c0), "+f"(c1), "+f"(c2), "+f"(c3)
        : "r"(a0), "r"(a1), "r"(a2), "r"(a3), "r"(b0), "r"(b1));
}
__device__ __forceinline__ void cp16(u32 dst, const void* src) {
    asm volatile("cp.async.cg.shared.global [%0], [%1], 16;" :: "r"(dst), "l"(src));
}
__device__ __forceinline__ u32 smem_u32(const void* p) {
    u32 a; asm("{ .reg .u64 t; cvta.to.shared.u64 t, %1; cvt.u32.u64 %0, t; }" : "=r"(a) : "l"(p));
    return a;
}

// ---------------- prep: W tf32-rna + bias sums (cheap) ----------------
__global__ void prep_w_kernel(const float* __restrict__ W, const float* __restrict__ b1,
                              const float* __restrict__ b2, float* __restrict__ wt,
                              float* __restrict__ bsum, int n)
{
    int i = blockIdx.x * 256 + threadIdx.x;
    if (i >= n) return;
    wt[i] = __uint_as_float(to_tf32(W[i]));
    if (i < Gd) bsum[i] = b1[i] + b2[i];
}

// ---------------------------------------------------------------------------
// Pipelined TF32 GEMM -> fp16 output: out[m,g] = sum_k A[m,k]*W[g,k] + bsum[g]
// CTA tile 128m x 64n, kc=32 double-buffered via cp.async.
// Warps: 4(m) x 2(n); per warp 32m x 32n = 2 x 4 m16n8k8 tiles.
// X_LAYOUT=true: A is x (B,S,C), row for m=(s*Bd+b) at (b*Sd+s)*K (raw fp32,
// tf32 truncation in HW). X_LAYOUT=false: A m-major (pre-rounded y1).
// ---------------------------------------------------------------------------
template <int K, bool X_LAYOUT>
__global__ __launch_bounds__(256) void gemm_tf32_kernel(
    const float* __restrict__ A, const float* __restrict__ Wt,
    const float* __restrict__ bsum, __half* __restrict__ out)
{
    constexpr int KC = 32;
    constexpr int NC = K / KC;
    constexpr int SK = 36;
    constexpr int ABUF = 128 * SK;
    constexpr int WBUF = 64 * SK;

    extern __shared__ u32 sm32[];
    const u32 sb = smem_u32(sm32);
    const u32 sA = sb;
    const u32 sW = sb + 2 * ABUF * 4;

    const int tid = threadIdx.x;
    const int mt  = blockIdx.x;
    const int nt  = blockIdx.y;

    auto fill = [&](int c, int buf) {
        const int k0 = c * KC;
#pragma unroll
        for (int r = 0; r < 4; r++) {
            int idx = tid + 256 * r;
            int row = idx >> 3, seg = idx & 7;
            int m = mt * 128 + row;
            const float* arow;
            if (X_LAYOUT) {
                int s = m >> 8, b = m & 255;
                arow = A + ((size_t)b * Sd + s) * K;
            } else {
                arow = A + (size_t)m * K;
            }
            cp16(sA + (u32)(buf * ABUF + row * SK + seg * 4) * 4, arow + k0 + seg * 4);
        }
#pragma unroll
        for (int r = 0; r < 2; r++) {
            int idx = tid + 256 * r;
            int row = idx >> 3, seg = idx & 7;
            cp16(sW + (u32)(buf * WBUF + row * SK + seg * 4) * 4,
                 Wt + (size_t)(nt * 64 + row) * K + k0 + seg * 4);
        }
        asm volatile("cp.async.commit_group;" ::: "memory");
    };

    const int wid  = tid >> 5;
    const int lane = tid & 31;
    const int gID  = lane >> 2;
    const int tig  = lane & 3;
    const int wm   = (wid >> 1) * 32;
    const int wn   = (wid & 1) * 32;

    float c[2][4][4];
#pragma unroll
    for (int i = 0; i < 2; i++)
#pragma unroll
        for (int j = 0; j < 4; j++)
#pragma unroll
            for (int q = 0; q < 4; q++) c[i][j][q] = 0.0f;

    fill(0, 0);

    for (int ch = 0; ch < NC; ch++) {
        if (ch + 1 < NC) {
            fill(ch + 1, (ch + 1) & 1);
            asm volatile("cp.async.wait_group 1;" ::: "memory");
        } else {
            asm volatile("cp.async.wait_group 0;" ::: "memory");
        }
        __syncthreads();

        const u32* As = sm32 + (ch & 1) * ABUF;
        const u32* Bs = sm32 + 2 * ABUF + (ch & 1) * WBUF;

#pragma unroll
        for (int kb = 0; kb < KC / 8; kb++) {
            const int k0 = kb * 8;
            u32 a[2][4];
#pragma unroll
            for (int mi = 0; mi < 2; mi++) {
                int r = wm + mi * 16 + gID;
                a[mi][0] = As[r * SK + k0 + tig];
                a[mi][1] = As[(r + 8) * SK + k0 + tig];
                a[mi][2] = As[r * SK + k0 + tig + 4];
                a[mi][3] = As[(r + 8) * SK + k0 + tig + 4];
            }
            u32 b[4][2];
#pragma unroll
            for (int ni = 0; ni < 4; ni++) {
                int r = wn + ni * 8 + gID;
                b[ni][0] = Bs[r * SK + k0 + tig];
                b[ni][1] = Bs[r * SK + k0 + tig + 4];
            }
#pragma unroll
            for (int mi = 0; mi < 2; mi++)
#pragma unroll
                for (int ni = 0; ni < 4; ni++)
                    mma_tf32(c[mi][ni][0], c[mi][ni][1], c[mi][ni][2], c[mi][ni][3],
                             a[mi][0], a[mi][1], a[mi][2], a[mi][3],
                             b[ni][0], b[ni][1]);
        }
        __syncthreads();
    }

    // epilogue: bias + fp16 store (half2; 4 tig lanes form 16B sectors)
#pragma unroll
    for (int ni = 0; ni < 4; ni++) {
        int g = nt * 64 + wn + ni * 8 + 2 * tig;
        float2 bv = *(const float2*)&bsum[g];
#pragma unroll
        for (int mi = 0; mi < 2; mi++) {
            size_t m = (size_t)mt * 128 + wm + mi * 16 + gID;
            *(__half2*)&out[m * Gd + g] =
                __floats2half2_rn(c[mi][ni][0] + bv.x, c[mi][ni][1] + bv.y);
            *(__half2*)&out[(m + 8) * Gd + g] =
                __floats2half2_rn(c[mi][ni][2] + bv.x, c[mi][ni][3] + bv.y);
        }
    }
}

// ---------------------------------------------------------------------------
// LSTM recurrence (proven core); xg now fp16. YIMG: layer 0 writes
// rna-rounded h m-major into g_y1; else writes only final h (fp32).
// ---------------------------------------------------------------------------
template <bool YIMG>
__global__ __launch_bounds__(REC_THREADS, 1) void lstm_rec_kernel(
    const __half* __restrict__ xg, const float* __restrict__ Whh,
    float* __restrict__ y_all, float* __restrict__ y_last)
{
    extern __shared__ char smraw[];
    ulonglong2* Wq = (ulonglong2*)smraw;
    float* hb = (float*)(smraw + (size_t)QS * 2 * 256 * 16);

    const int t = threadIdx.x;
    const int u = t >> 1;
    const int p = t & 1;
    const int col0 = p * 128 + u;
    const int col1 = 256 + p * 128 + u;
    const int b0 = blockIdx.x * 2;

    u64 wA[2 * QR], wB[2 * QR];
    {
        const u64* rowA = (const u64*)(Whh + (size_t)col0 * Hd);
        const u64* rowB = (const u64*)(Whh + (size_t)col1 * Hd);
#pragma unroll
        for (int j = 0; j < 2 * QR; j++) { wA[j] = rowA[j]; wB[j] = rowB[j]; }
    }
#pragma unroll
    for (int j = 0; j < QS; j++) {
        Wq[(j * 2 + 0) * 256 + t] = *(const ulonglong2*)(Whh + (size_t)col0 * Hd + KR + 4 * j);
        Wq[(j * 2 + 1) * 256 + t] = *(const ulonglong2*)(Whh + (size_t)col1 * Hd + KR + 4 * j);
    }
    for (int i = t; i < 2 * 2 * 132; i += REC_THREADS) hb[i] = 0.0f;

    float c = 0.0f;
    __syncthreads();

    float xv00 = __half2float(xg[(size_t)(b0)*Gd + col0]);
    float xv01 = __half2float(xg[(size_t)(b0 + 1) * Gd + col0]);
    float xv10 = __half2float(xg[(size_t)(b0)*Gd + col1]);
    float xv11 = __half2float(xg[(size_t)(b0 + 1) * Gd + col1]);

    for (int s = 0; s < Sd; s++) {
        float n00 = 0.f, n01 = 0.f, n10 = 0.f, n11 = 0.f;
        if (s + 1 < Sd) {
            size_t base = (size_t)(s + 1) * Bd + b0;
            n00 = __half2float(xg[base * Gd + col0]);
            n01 = __half2float(xg[(base + 1) * Gd + col0]);
            n10 = __half2float(xg[base * Gd + col1]);
            n11 = __half2float(xg[(base + 1) * Gd + col1]);
        }
        const int ph = s & 1;
        const ulonglong2* hq0 = (const ulonglong2*)(hb + (ph * 2 + 0) * 132);
        const ulonglong2* hq1 = (const ulonglong2*)(hb + (ph * 2 + 1) * 132);

        u64 a00e = 0, a00o = 0, a01e = 0, a01o = 0;
        u64 a10e = 0, a10o = 0, a11e = 0, a11o = 0;

#pragma unroll
        for (int j = 0; j < QR; j++) {
            ulonglong2 hA = hq0[j], hB = hq1[j];
            a00e = fma2(wA[2 * j], hA.x, a00e);
            a00o = fma2(wA[2 * j + 1], hA.y, a00o);
            a01e = fma2(wA[2 * j], hB.x, a01e);
            a01o = fma2(wA[2 * j + 1], hB.y, a01o);
            a10e = fma2(wB[2 * j], hA.x, a10e);
            a10o = fma2(wB[2 * j + 1], hA.y, a10o);
            a11e = fma2(wB[2 * j], hB.x, a11e);
            a11o = fma2(wB[2 * j + 1], hB.y, a11o);
        }
#pragma unroll
        for (int j = 0; j < QS; j++) {
            ulonglong2 w0 = Wq[(j * 2 + 0) * 256 + t];
            ulonglong2 w1 = Wq[(j * 2 + 1) * 256 + t];
            ulonglong2 hA = hq0[QR + j], hB = hq1[QR + j];
            a00e = fma2(w0.x, hA.x, a00e);
            a00o = fma2(w0.y, hA.y, a00o);
            a01e = fma2(w0.x, hB.x, a01e);
            a01o = fma2(w0.y, hB.y, a01o);
            a10e = fma2(w1.x, hA.x, a10e);
            a10o = fma2(w1.y, hA.y, a10o);
            a11e = fma2(w1.x, hB.x, a11e);
            a11o = fma2(w1.y, hB.y, a11o);
        }

        float p00 = xv00 + hsum2(a00e) + hsum2(a00o);
        float p01 = xv01 + hsum2(a01e) + hsum2(a01o);
        float p10 = xv10 + hsum2(a10e) + hsum2(a10o);
        float p11 = xv11 + hsum2(a11e) + hsum2(a11o);

        float v00 = fmaf(0.5f, tanh_fast(0.5f * p00), 0.5f);
        float v01 = fmaf(0.5f, tanh_fast(0.5f * p01), 0.5f);
        float a10s = (p == 0) ? p10 : 0.5f * p10;
        float a11s = (p == 0) ? p11 : 0.5f * p11;
        float t10 = tanh_fast(a10s);
        float t11 = tanh_fast(a11s);
        float v10 = (p == 0) ? t10 : fmaf(0.5f, t10, 0.5f);
        float v11 = (p == 0) ? t11 : fmaf(0.5f, t11, 0.5f);

        float send1 = (p == 0) ? v01 : v00;
        float send2 = (p == 0) ? v11 : v10;
        float got1 = __shfl_xor_sync(0xffffffffu, send1, 1);
        float got2 = __shfl_xor_sync(0xffffffffu, send2, 1);

        float iv = (p == 0) ? v00 : got1;
        float fv = (p == 0) ? got1 : v01;
        float gv = (p == 0) ? v10 : got2;
        float ov = (p == 0) ? got2 : v11;

        c = fmaf(fv, c, iv * gv);
        float hn = ov * tanh_fast(c);

        hb[((ph ^ 1) * 2 + p) * 132 + u] = hn;
        if (YIMG) {
            y_all[((size_t)s * Bd + b0 + p) * Hd + u] = __uint_as_float(to_tf32(hn));
        } else if (s == Sd - 1) {
            y_last[(size_t)(b0 + p) * Hd + u] = hn;
        }

        xv00 = n00; xv01 = n01; xv10 = n10; xv11 = n11;
        __syncthreads();
    }
}

// ---------------------------------------------------------------------------
extern "C" void kernel_launch(void* const* d_in, const int* in_sizes, int n_in,
                              void* d_out, int out_size)
{
    const float* x    = (const float*)d_in[0];
    const float* Wih0 = (const float*)d_in[1];
    const float* Whh0 = (const float*)d_in[2];
    const float* bih0 = (const float*)d_in[3];
    const float* bhh0 = (const float*)d_in[4];
    const float* Wih1 = (const float*)d_in[5];
    const float* Whh1 = (const float*)d_in[6];
    const float* bih1 = (const float*)d_in[7];
    const float* bhh1 = (const float*)d_in[8];
    float* out = (float*)d_out;

    __half* xg;
    float *y1, *w0t, *w1t, *bs0, *bs1;
    cudaGetSymbolAddress((void**)&xg, g_xg);
    cudaGetSymbolAddress((void**)&y1, g_y1);
    cudaGetSymbolAddress((void**)&w0t, g_w0t);
    cudaGetSymbolAddress((void**)&w1t, g_w1t);
    cudaGetSymbolAddress((void**)&bs0, g_bs0);
    cudaGetSymbolAddress((void**)&bs1, g_bs1);

    const int smem_gemm = (2 * 128 * 36 + 2 * 64 * 36) * 4;   // 55296 B
    const int smem_rec  = QS * 2 * 256 * 16 + 2 * 2 * 132 * (int)sizeof(float);

    cudaFuncSetAttribute((const void*)gemm_tf32_kernel<Cd, true>,
                         cudaFuncAttributeMaxDynamicSharedMemorySize, smem_gemm);
    cudaFuncSetAttribute((const void*)gemm_tf32_kernel<Hd, false>,
                         cudaFuncAttributeMaxDynamicSharedMemorySize, smem_gemm);
    cudaFuncSetAttribute((const void*)lstm_rec_kernel<true>,
                         cudaFuncAttributeMaxDynamicSharedMemorySize, smem_rec);
    cudaFuncSetAttribute((const void*)lstm_rec_kernel<false>,
                         cudaFuncAttributeMaxDynamicSharedMemorySize, smem_rec);

    // cheap preps: W -> tf32 rna, bias sums
    prep_w_kernel<<<(Gd * Cd + 255) / 256, 256>>>(Wih0, bih0, bhh0, w0t, bs0, Gd * Cd);
    prep_w_kernel<<<(Gd * Hd + 255) / 256, 256>>>(Wih1, bih1, bhh1, w1t, bs1, Gd * Hd);

    dim3 ggrid((Sd * Bd) / 128, Gd / 64);

    // layer 0
    gemm_tf32_kernel<Cd, true><<<ggrid, 256, smem_gemm>>>(x, w0t, bs0, xg);
    lstm_rec_kernel<true><<<Bd / 2, REC_THREADS, smem_rec>>>(xg, Whh0, y1, nullptr);

    // layer 1
    gemm_tf32_kernel<Hd, false><<<ggrid, 256, smem_gemm>>>(y1, w1t, bs1, xg);
    lstm_rec_kernel<false><<<Bd / 2, REC_THREADS, smem_rec>>>(xg, Whh1, nullptr, out);
}

// round 13
// speedup vs baseline: 1.0623x; 1.0424x over previous
#include <cuda_runtime.h>
#include <cuda_fp16.h>
#include <cstdint>

#define Bd 256
#define Sd 512
#define Cd 64
#define Hd 128
#define Gd 512
#define REC_THREADS 256
#define KR 80
#define QR 20
#define QS 12

typedef unsigned long long u64;
typedef unsigned int u32;

// ---------------- device global scratch ----------------
__device__ __half g_xg[(size_t)Sd * Bd * Gd];     // gate preacts, fp16
__device__ __half g_a0[(size_t)Sd * Bd * Cd];     // x, fp16, m-major
__device__ __half g_y1h[(size_t)Sd * Bd * Hd];    // layer-0 h, fp16, m-major
__device__ __half g_w0h[(size_t)Gd * Cd];         // Wih0 fp16
__device__ __half g_w1h[(size_t)Gd * Hd];         // Wih1 fp16
__device__ float  g_bs0[Gd];
__device__ float  g_bs1[Gd];

// ---------------- helpers ----------------
__device__ __forceinline__ void unpack2(u64 v, float& x, float& y) {
    asm("mov.b64 {%0,%1}, %2;" : "=f"(x), "=f"(y) : "l"(v));
}
__device__ __forceinline__ u64 fma2(u64 a, u64 b, u64 c) {
    u64 d; asm("fma.rn.f32x2 %0, %1, %2, %3;" : "=l"(d) : "l"(a), "l"(b), "l"(c)); return d;
}
__device__ __forceinline__ float tanh_fast(float x) {
    float y; asm("tanh.approx.f32 %0, %1;" : "=f"(y) : "f"(x)); return y;
}
__device__ __forceinline__ float hsum2(u64 v) { float a, b; unpack2(v, a, b); return a + b; }
__device__ __forceinline__ void mma_f16(
    float& c0, float& c1, float& c2, float& c3,
    u32 a0, u32 a1, u32 a2, u32 a3, u32 b0, u32 b1)
{
    asm("mma.sync.aligned.m16n8k16.row.col.f32.f16.f16.f32 "
        "{%0,%1,%2,%3}, {%4,%5,%6,%7}, {%8,%9}, {%0,%1,%2,%3};"
        : "+f"(c0), "+f"(c1), "+f"(c2), "+f"(c3)
        : "r"(a0), "r"(a1), "r"(a2), "r"(a3), "r"(b0), "r"(b1));
}
__device__ __forceinline__ void cp16(u32 dst, const void* src) {
    asm volatile("cp.async.cg.shared.global [%0], [%1], 16;" :: "r"(dst), "l"(src));
}
__device__ __forceinline__ u32 smem_u32(const void* p) {
    u32 a; asm("{ .reg .u64 t; cvta.to.shared.u64 t, %1; cvt.u32.u64 %0, t; }" : "=r"(a) : "l"(p));
    return a;
}

// ---------------- prep kernels ----------------
__global__ void prep_x_kernel(const float* __restrict__ x)
{
    int i = blockIdx.x * 256 + threadIdx.x;          // linear over x (B,S,C)
    if (i >= Bd * Sd * Cd) return;
    int k = i & (Cd - 1);
    int s = (i >> 6) & (Sd - 1);
    int b = i >> 15;
    g_a0[((size_t)(s * Bd + b)) * Cd + k] = __float2half(x[i]);
}

__global__ void prep_w_kernel(const float* __restrict__ W, const float* __restrict__ b1,
                              const float* __restrict__ b2, __half* __restrict__ wh,
                              float* __restrict__ bsum, int n)
{
    int i = blockIdx.x * 256 + threadIdx.x;
    if (i >= n) return;
    wh[i] = __float2half(W[i]);
    if (i < Gd) bsum[i] = b1[i] + b2[i];
}

// ---------------------------------------------------------------------------
// Pipelined FP16 GEMM (fp32 accum): out[m,g] = sum_k A[m,k]*W[g,k] + bsum[g]
// A m-major fp16 [m][K]; W fp16 [g][K]. CTA tile 128m x 128n, kc=32 elements,
// double-buffered cp.async. Warps 4m x 2n; per warp 32m x 64n = 2 x 8
// m16n8k16 tiles. Smem rows: 32 halves (64B) + 16B pad -> u32 stride 20;
// banks (20*gID + tig) all-distinct -> conflict-free fragment loads.
// ---------------------------------------------------------------------------
template <int K>
__global__ __launch_bounds__(256) void gemm_f16_kernel(
    const __half* __restrict__ A, const __half* __restrict__ Wh,
    const float* __restrict__ bsum, __half* __restrict__ out)
{
    constexpr int KC = 32;                 // k elements per chunk
    constexpr int NC = K / KC;
    constexpr int SKW = 20;                // u32 stride per row (64B data + 16B pad)
    constexpr int TBUF = 128 * SKW;        // u32 per matrix per stage

    extern __shared__ u32 sm32[];
    const u32 sb = smem_u32(sm32);

    const int tid = threadIdx.x;
    const int mt  = blockIdx.x;
    const int nt  = blockIdx.y;

    auto fill = [&](int c, int buf) {
        const int k0 = c * KC;
        // A: 128 rows x 4 segs of 16B
#pragma unroll
        for (int r = 0; r < 2; r++) {
            int task = tid + 256 * r;
            int row = task >> 2, seg = task & 3;
            cp16(sb + (u32)(buf * 2 * TBUF + row * SKW + seg * 4) * 4,
                 (const char*)(A + (size_t)(mt * 128 + row) * K + k0) + seg * 16);
        }
        // W: 128 rows x 4 segs
#pragma unroll
        for (int r = 0; r < 2; r++) {
            int task = tid + 256 * r;
            int row = task >> 2, seg = task & 3;
            cp16(sb + (u32)(buf * 2 * TBUF + TBUF + row * SKW + seg * 4) * 4,
                 (const char*)(Wh + (size_t)(nt * 128 + row) * K + k0) + seg * 16);
        }
        asm volatile("cp.async.commit_group;" ::: "memory");
    };

    const int wid  = tid >> 5;
    const int lane = tid & 31;
    const int gID  = lane >> 2;
    const int tig  = lane & 3;
    const int wm   = (wid >> 1) * 32;      // 4 m-warps
    const int wn   = (wid & 1) * 64;       // 2 n-warps

    float c[2][8][4];
#pragma unroll
    for (int i = 0; i < 2; i++)
#pragma unroll
        for (int j = 0; j < 8; j++)
#pragma unroll
            for (int q = 0; q < 4; q++) c[i][j][q] = 0.0f;

    fill(0, 0);

    for (int ch = 0; ch < NC; ch++) {
        if (ch + 1 < NC) {
            fill(ch + 1, (ch + 1) & 1);
            asm volatile("cp.async.wait_group 1;" ::: "memory");
        } else {
            asm volatile("cp.async.wait_group 0;" ::: "memory");
        }
        __syncthreads();

        const u32* As = sm32 + (ch & 1) * 2 * TBUF;
        const u32* Bs = As + TBUF;

#pragma unroll
        for (int ks = 0; ks < KC / 16; ks++) {     // k16 steps
            const int kw = ks * 8;                  // u32 offset within row
            u32 a[2][4];
#pragma unroll
            for (int mi = 0; mi < 2; mi++) {
                int r = wm + mi * 16 + gID;
                a[mi][0] = As[r * SKW + kw + tig];
                a[mi][1] = As[(r + 8) * SKW + kw + tig];
                a[mi][2] = As[r * SKW + kw + tig + 4];
                a[mi][3] = As[(r + 8) * SKW + kw + tig + 4];
            }
            u32 b[8][2];
#pragma unroll
            for (int ni = 0; ni < 8; ni++) {
                int r = wn + ni * 8 + gID;
                b[ni][0] = Bs[r * SKW + kw + tig];
                b[ni][1] = Bs[r * SKW + kw + tig + 4];
            }
#pragma unroll
            for (int mi = 0; mi < 2; mi++)
#pragma unroll
                for (int ni = 0; ni < 8; ni++)
                    mma_f16(c[mi][ni][0], c[mi][ni][1], c[mi][ni][2], c[mi][ni][3],
                            a[mi][0], a[mi][1], a[mi][2], a[mi][3],
                            b[ni][0], b[ni][1]);
        }
        __syncthreads();
    }

    // epilogue: bias + fp16 half2 stores
#pragma unroll
    for (int ni = 0; ni < 8; ni++) {
        int g = nt * 128 + wn + ni * 8 + 2 * tig;
        float2 bv = *(const float2*)&bsum[g];
#pragma unroll
        for (int mi = 0; mi < 2; mi++) {
            size_t m = (size_t)mt * 128 + wm + mi * 16 + gID;
            *(__half2*)&out[m * Gd + g] =
                __floats2half2_rn(c[mi][ni][0] + bv.x, c[mi][ni][1] + bv.y);
            *(__half2*)&out[(m + 8) * Gd + g] =
                __floats2half2_rn(c[mi][ni][2] + bv.x, c[mi][ni][3] + bv.y);
        }
    }
}

// ---------------------------------------------------------------------------
// LSTM recurrence (proven fma-floor core); xg fp16 (raw __half regs,
// convert at use). YIMG: layer 0 writes h fp16 m-major into g_y1h;
// else writes only final h (fp32) to y_last.
// ---------------------------------------------------------------------------
template <bool YIMG>
__global__ __launch_bounds__(REC_THREADS, 1) void lstm_rec_kernel(
    const __half* __restrict__ xg, const float* __restrict__ Whh,
    __half* __restrict__ y_img, float* __restrict__ y_last)
{
    extern __shared__ char smraw[];
    ulonglong2* Wq = (ulonglong2*)smraw;
    float* hb = (float*)(smraw + (size_t)QS * 2 * 256 * 16);

    const int t = threadIdx.x;
    const int u = t >> 1;
    const int p = t & 1;
    const int col0 = p * 128 + u;
    const int col1 = 256 + p * 128 + u;
    const int b0 = blockIdx.x * 2;

    u64 wA[2 * QR], wB[2 * QR];
    {
        const u64* rowA = (const u64*)(Whh + (size_t)col0 * Hd);
        const u64* rowB = (const u64*)(Whh + (size_t)col1 * Hd);
#pragma unroll
        for (int j = 0; j < 2 * QR; j++) { wA[j] = rowA[j]; wB[j] = rowB[j]; }
    }
#pragma unroll
    for (int j = 0; j < QS; j++) {
        Wq[(j * 2 + 0) * 256 + t] = *(const ulonglong2*)(Whh + (size_t)col0 * Hd + KR + 4 * j);
        Wq[(j * 2 + 1) * 256 + t] = *(const ulonglong2*)(Whh + (size_t)col1 * Hd + KR + 4 * j);
    }
    for (int i = t; i < 2 * 2 * 132; i += REC_THREADS) hb[i] = 0.0f;

    float c = 0.0f;
    __syncthreads();

    __half xh00 = xg[(size_t)(b0)*Gd + col0];
    __half xh01 = xg[(size_t)(b0 + 1) * Gd + col0];
    __half xh10 = xg[(size_t)(b0)*Gd + col1];
    __half xh11 = xg[(size_t)(b0 + 1) * Gd + col1];

    for (int s = 0; s < Sd; s++) {
        __half nh00, nh01, nh10, nh11;
        if (s + 1 < Sd) {
            size_t base = (size_t)(s + 1) * Bd + b0;
            nh00 = xg[base * Gd + col0];
            nh01 = xg[(base + 1) * Gd + col0];
            nh10 = xg[base * Gd + col1];
            nh11 = xg[(base + 1) * Gd + col1];
        } else {
            nh00 = nh01 = nh10 = nh11 = __half(0.0f);
        }
        const int ph = s & 1;
        const ulonglong2* hq0 = (const ulonglong2*)(hb + (ph * 2 + 0) * 132);
        const ulonglong2* hq1 = (const ulonglong2*)(hb + (ph * 2 + 1) * 132);

        u64 a00e = 0, a00o = 0, a01e = 0, a01o = 0;
        u64 a10e = 0, a10o = 0, a11e = 0, a11o = 0;

#pragma unroll
        for (int j = 0; j < QR; j++) {
            ulonglong2 hA = hq0[j], hB = hq1[j];
            a00e = fma2(wA[2 * j], hA.x, a00e);
            a00o = fma2(wA[2 * j + 1], hA.y, a00o);
            a01e = fma2(wA[2 * j], hB.x, a01e);
            a01o = fma2(wA[2 * j + 1], hB.y, a01o);
            a10e = fma2(wB[2 * j], hA.x, a10e);
            a10o = fma2(wB[2 * j + 1], hA.y, a10o);
            a11e = fma2(wB[2 * j], hB.x, a11e);
            a11o = fma2(wB[2 * j + 1], hB.y, a11o);
        }
#pragma unroll
        for (int j = 0; j < QS; j++) {
            ulonglong2 w0 = Wq[(j * 2 + 0) * 256 + t];
            ulonglong2 w1 = Wq[(j * 2 + 1) * 256 + t];
            ulonglong2 hA = hq0[QR + j], hB = hq1[QR + j];
            a00e = fma2(w0.x, hA.x, a00e);
            a00o = fma2(w0.y, hA.y, a00o);
            a01e = fma2(w0.x, hB.x, a01e);
            a01o = fma2(w0.y, hB.y, a01o);
            a10e = fma2(w1.x, hA.x, a10e);
            a10o = fma2(w1.y, hA.y, a10o);
            a11e = fma2(w1.x, hB.x, a11e);
            a11o = fma2(w1.y, hB.y, a11o);
        }

        float p00 = __half2float(xh00) + hsum2(a00e) + hsum2(a00o);
        float p01 = __half2float(xh01) + hsum2(a01e) + hsum2(a01o);
        float p10 = __half2float(xh10) + hsum2(a10e) + hsum2(a10o);
        float p11 = __half2float(xh11) + hsum2(a11e) + hsum2(a11o);

        float v00 = fmaf(0.5f, tanh_fast(0.5f * p00), 0.5f);
        float v01 = fmaf(0.5f, tanh_fast(0.5f * p01), 0.5f);
        float a10s = (p == 0) ? p10 : 0.5f * p10;
        float a11s = (p == 0) ? p11 : 0.5f * p11;
        float t10 = tanh_fast(a10s);
        float t11 = tanh_fast(a11s);
        float v10 = (p == 0) ? t10 : fmaf(0.5f, t10, 0.5f);
        float v11 = (p == 0) ? t11 : fmaf(0.5f, t11, 0.5f);

        float send1 = (p == 0) ? v01 : v00;
        float send2 = (p == 0) ? v11 : v10;
        float got1 = __shfl_xor_sync(0xffffffffu, send1, 1);
        float got2 = __shfl_xor_sync(0xffffffffu, send2, 1);

        float iv = (p == 0) ? v00 : got1;
        float fv = (p == 0) ? got1 : v01;
        float gv = (p == 0) ? v10 : got2;
        float ov = (p == 0) ? got2 : v11;

        c = fmaf(fv, c, iv * gv);
        float hn = ov * tanh_fast(c);

        hb[((ph ^ 1) * 2 + p) * 132 + u] = hn;
        if (YIMG) {
            y_img[((size_t)s * Bd + b0 + p) * Hd + u] = __float2half(hn);
        } else if (s == Sd - 1) {
            y_last[(size_t)(b0 + p) * Hd + u] = hn;
        }

        xh00 = nh00; xh01 = nh01; xh10 = nh10; xh11 = nh11;
        __syncthreads();
    }
}

// ---------------------------------------------------------------------------
extern "C" void kernel_launch(void* const* d_in, const int* in_sizes, int n_in,
                              void* d_out, int out_size)
{
    const float* x    = (const float*)d_in[0];
    const float* Wih0 = (const float*)d_in[1];
    const float* Whh0 = (const float*)d_in[2];
    const float* bih0 = (const float*)d_in[3];
    const float* bhh0 = (const float*)d_in[4];
    const float* Wih1 = (const float*)d_in[5];
    const float* Whh1 = (const float*)d_in[6];
    const float* bih1 = (const float*)d_in[7];
    const float* bhh1 = (const float*)d_in[8];
    float* out = (float*)d_out;

    __half *xg, *a0, *y1h, *w0h, *w1h;
    float *bs0, *bs1;
    cudaGetSymbolAddress((void**)&xg, g_xg);
    cudaGetSymbolAddress((void**)&a0, g_a0);
    cudaGetSymbolAddress((void**)&y1h, g_y1h);
    cudaGetSymbolAddress((void**)&w0h, g_w0h);
    cudaGetSymbolAddress((void**)&w1h, g_w1h);
    cudaGetSymbolAddress((void**)&bs0, g_bs0);
    cudaGetSymbolAddress((void**)&bs1, g_bs1);

    const int smem_gemm = 2 * 2 * 128 * 20 * 4;   // 40960 B
    const int smem_rec  = QS * 2 * 256 * 16 + 2 * 2 * 132 * (int)sizeof(float);

    cudaFuncSetAttribute((const void*)gemm_f16_kernel<Cd>,
                         cudaFuncAttributeMaxDynamicSharedMemorySize, smem_gemm);
    cudaFuncSetAttribute((const void*)gemm_f16_kernel<Hd>,
                         cudaFuncAttributeMaxDynamicSharedMemorySize, smem_gemm);
    cudaFuncSetAttribute((const void*)lstm_rec_kernel<true>,
                         cudaFuncAttributeMaxDynamicSharedMemorySize, smem_rec);
    cudaFuncSetAttribute((const void*)lstm_rec_kernel<false>,
                         cudaFuncAttributeMaxDynamicSharedMemorySize, smem_rec);

    // preps: x -> fp16 m-major; W -> fp16; bias sums
    prep_x_kernel<<<(Bd * Sd * Cd + 255) / 256, 256>>>(x);
    prep_w_kernel<<<(Gd * Cd + 255) / 256, 256>>>(Wih0, bih0, bhh0, w0h, bs0, Gd * Cd);
    prep_w_kernel<<<(Gd * Hd + 255) / 256, 256>>>(Wih1, bih1, bhh1, w1h, bs1, Gd * Hd);

    dim3 ggrid((Sd * Bd) / 128, Gd / 128);

    // layer 0
    gemm_f16_kernel<Cd><<<ggrid, 256, smem_gemm>>>(a0, w0h, bs0, xg);
    lstm_rec_kernel<true><<<Bd / 2, REC_THREADS, smem_rec>>>(xg, Whh0, y1h, nullptr);

    // layer 1
    gemm_f16_kernel<Hd><<<ggrid, 256, smem_gemm>>>(y1h, w1h, bs1, xg);
    lstm_rec_kernel<false><<<Bd / 2, REC_THREADS, smem_rec>>>(xg, Whh1, nullptr, out);
}